// round 7
// baseline (speedup 1.0000x reference)
#include <cuda_runtime.h>
#include <cstdint>
#include <math.h>

// Problem constants (fixed by the dataset)
#define BATCH 4
#define SEQL  2048
#define NH    8
#define HDIM  64      // E == D == 64
#define BM    128     // query rows per CTA (4 warps x 32 rows)
#define BN    64      // key rows per iteration
#define KSTR  68      // sK row stride — conflict-free for QK B-frags
#define VSTR  72      // sV row stride — conflict-free for PV B-frags
#define PSTR  68      // sP row stride — conflict-free for P A-frags
#define RS    (NH * HDIM)                      // 512 floats between seq positions
#define STAGE_FLOATS (BN * KSTR + BN * VSTR)   // 8960 floats per stage
#define SP_OFF (2 * STAGE_FLOATS)              // 17920
#define SMEM_FLOATS (SP_OFF + BM * PSTR)       // 26624
#define SMEM_BYTES  (SMEM_FLOATS * 4)          // 106496

__device__ __forceinline__ uint32_t f2tf32(float f) {
    uint32_t u;
    asm("cvt.rna.tf32.f32 %0, %1;" : "=r"(u) : "f"(f));
    return u;
}
__device__ __forceinline__ float f2tf32f(float f) {
    return __uint_as_float(f2tf32(f));
}
__device__ __forceinline__ float ex2(float x) {
    float y;
    asm("ex2.approx.ftz.f32 %0, %1;" : "=f"(y) : "f"(x));
    return y;
}

__device__ __forceinline__ void mma8(float c[4], const uint32_t a[4], const uint32_t b[2]) {
    asm volatile(
        "mma.sync.aligned.m16n8k8.row.col.f32.tf32.tf32.f32 "
        "{%0,%1,%2,%3}, {%4,%5,%6,%7}, {%8,%9}, {%0,%1,%2,%3};"
        : "+f"(c[0]), "+f"(c[1]), "+f"(c[2]), "+f"(c[3])
        : "r"(a[0]), "r"(a[1]), "r"(a[2]), "r"(a[3]),
          "r"(b[0]), "r"(b[1]));
}

__device__ __forceinline__ void cpasync16(uint32_t saddr, const float* g) {
    asm volatile("cp.async.cg.shared.global [%0], [%1], 16;\n"
                 :: "r"(saddr), "l"(g));
}

__global__ __launch_bounds__(128, 2)
void fa_tf32_kernel(const float* __restrict__ Q,
                    const float* __restrict__ K,
                    const float* __restrict__ V,
                    float* __restrict__ O)
{
    extern __shared__ float smem[];

    const int tid  = threadIdx.x;
    const int warp = tid >> 5;
    const int lane = tid & 31;
    const int qd   = lane & 3;    // thread-in-group
    const int g    = lane >> 2;   // group id

    const int bh = blockIdx.y;
    const int b  = bh >> 3;       // NH = 8
    const int h  = bh & 7;
    // heavy tiles first
    const int qblk = (SEQL / BM - 1) - blockIdx.x;
    const int m0   = qblk * BM;
    const int nblk = 2 * qblk + 2;   // key tiles 0 .. 2*qblk+1

    // softmax scale folded into Q: scores come out in log2 domain
    const float qscale = 0.125f * 1.4426950408889634f;

    const float* Qb = Q + ((size_t)((size_t)b * SEQL + m0) * NH + h) * HDIM;
    const float* Kb = K + ((size_t)((size_t)b * SEQL) * NH + h) * HDIM;
    const float* Vb = V + ((size_t)((size_t)b * SEQL) * NH + h) * HDIM;

    float* const stage0 = smem;
    float* const stage1 = smem + STAGE_FLOATS;
    float* const sP     = smem + SP_OFF;     // Q staging, then P buffer

    // ---- prologue: async-load K/V tile 0 into stage0
    #pragma unroll
    for (int i = 0; i < 8; i++) {
        int idx = i * 128 + tid;          // 64 rows x 16 float4
        int r   = idx >> 4;
        int c4  = (idx & 15) << 2;
        size_t goff = (size_t)r * RS + c4;
        cpasync16((uint32_t)__cvta_generic_to_shared(stage0 + r * KSTR + c4), Kb + goff);
        cpasync16((uint32_t)__cvta_generic_to_shared(stage0 + BN * KSTR + r * VSTR + c4), Vb + goff);
    }
    asm volatile("cp.async.commit_group;\n");

    // ---- stage Q (raw) into sP area (128 rows x stride 68)
    #pragma unroll
    for (int i = 0; i < 16; i++) {
        int idx = i * 128 + tid;          // 128 rows x 16 float4
        int r   = idx >> 4;
        int c4  = (idx & 15) << 2;
        float4 v = *reinterpret_cast<const float4*>(Qb + (size_t)r * RS + c4);
        float* dst = &sP[r * PSTR + c4];
        dst[0] = v.x; dst[1] = v.y; dst[2] = v.z; dst[3] = v.w;
    }
    __syncthreads();

    // warp owns rows rw .. rw+31 (two 16-row MMA tiles)
    const int rw = warp * 32 + g;
    const int ga0 = m0 + rw,      ga1 = ga0 + 8;    // tile A rows
    const int gb0 = ga0 + 16,     gb1 = ga0 + 24;   // tile B rows

    uint32_t qa0[8][4], qa1[8][4];
    #pragma unroll
    for (int kk = 0; kk < 8; kk++) {
        qa0[kk][0] = f2tf32(sP[rw        * PSTR + kk * 8 + qd]     * qscale);
        qa0[kk][1] = f2tf32(sP[(rw + 8)  * PSTR + kk * 8 + qd]     * qscale);
        qa0[kk][2] = f2tf32(sP[rw        * PSTR + kk * 8 + qd + 4] * qscale);
        qa0[kk][3] = f2tf32(sP[(rw + 8)  * PSTR + kk * 8 + qd + 4] * qscale);
        qa1[kk][0] = f2tf32(sP[(rw + 16) * PSTR + kk * 8 + qd]     * qscale);
        qa1[kk][1] = f2tf32(sP[(rw + 24) * PSTR + kk * 8 + qd]     * qscale);
        qa1[kk][2] = f2tf32(sP[(rw + 16) * PSTR + kk * 8 + qd + 4] * qscale);
        qa1[kk][3] = f2tf32(sP[(rw + 24) * PSTR + kk * 8 + qd + 4] * qscale);
    }
    // no barrier needed: each warp read only its own sP rows, and will only
    // write its own sP rows (P) later.

    float o0[8][4], o1[8][4];
    #pragma unroll
    for (int n = 0; n < 8; n++)
        #pragma unroll
        for (int i = 0; i < 4; i++) { o0[n][i] = 0.f; o1[n][i] = 0.f; }

    float m00 = -INFINITY, m01 = -INFINITY, m10 = -INFINITY, m11 = -INFINITY;
    float l00 = 0.f, l01 = 0.f, l10 = 0.f, l11 = 0.f;

    for (int j = 0; j < nblk; j++) {
        float* const sK = (j & 1) ? stage1 : stage0;
        float* const sV = sK + BN * KSTR;

        asm volatile("cp.async.wait_group 0;\n");
        __syncthreads();   // tile j visible; everyone done with the other stage

        // ---- prefetch tile j+1 into the other stage
        if (j + 1 < nblk) {
            float* const nK = (j & 1) ? stage0 : stage1;
            float* const nV = nK + BN * KSTR;
            #pragma unroll
            for (int i = 0; i < 8; i++) {
                int idx = i * 128 + tid;
                int r   = idx >> 4;
                int c4  = (idx & 15) << 2;
                size_t goff = (size_t)((j + 1) * BN + r) * RS + c4;
                cpasync16((uint32_t)__cvta_generic_to_shared(nK + r * KSTR + c4), Kb + goff);
                cpasync16((uint32_t)__cvta_generic_to_shared(nV + r * VSTR + c4), Vb + goff);
            }
            asm volatile("cp.async.commit_group;\n");
        }

        // ---- S = Q K^T for both 16-row tiles; each K B-frag feeds 2 MMAs
        float c0[8][4], c1[8][4];
        #pragma unroll
        for (int n = 0; n < 8; n++)
            #pragma unroll
            for (int i = 0; i < 4; i++) { c0[n][i] = 0.f; c1[n][i] = 0.f; }

        #pragma unroll
        for (int kk = 0; kk < 8; kk++) {
            #pragma unroll
            for (int n = 0; n < 8; n++) {
                uint32_t bf[2];
                bf[0] = __float_as_uint(sK[(n * 8 + g) * KSTR + kk * 8 + qd]);
                bf[1] = __float_as_uint(sK[(n * 8 + g) * KSTR + kk * 8 + qd + 4]);
                mma8(c0[n], qa0[kk], bf);
                mma8(c1[n], qa1[kk], bf);
            }
        }

        // ---- causal mask (last two key tiles)
        if (j >= 2 * qblk) {
            #pragma unroll
            for (int n = 0; n < 8; n++) {
                int colb = j * BN + n * 8 + 2 * qd;
                if (colb     > ga0) c0[n][0] = -INFINITY;
                if (colb + 1 > ga0) c0[n][1] = -INFINITY;
                if (colb     > ga1) c0[n][2] = -INFINITY;
                if (colb + 1 > ga1) c0[n][3] = -INFINITY;
                if (colb     > gb0) c1[n][0] = -INFINITY;
                if (colb + 1 > gb0) c1[n][1] = -INFINITY;
                if (colb     > gb1) c1[n][2] = -INFINITY;
                if (colb + 1 > gb1) c1[n][3] = -INFINITY;
            }
        }

        // ---- online softmax (log2 domain), 4 row groups
        float t00 = -INFINITY, t01 = -INFINITY, t10 = -INFINITY, t11 = -INFINITY;
        #pragma unroll
        for (int n = 0; n < 8; n++) {
            t00 = fmaxf(t00, fmaxf(c0[n][0], c0[n][1]));
            t01 = fmaxf(t01, fmaxf(c0[n][2], c0[n][3]));
            t10 = fmaxf(t10, fmaxf(c1[n][0], c1[n][1]));
            t11 = fmaxf(t11, fmaxf(c1[n][2], c1[n][3]));
        }
        t00 = fmaxf(t00, __shfl_xor_sync(0xffffffffu, t00, 1));
        t00 = fmaxf(t00, __shfl_xor_sync(0xffffffffu, t00, 2));
        t01 = fmaxf(t01, __shfl_xor_sync(0xffffffffu, t01, 1));
        t01 = fmaxf(t01, __shfl_xor_sync(0xffffffffu, t01, 2));
        t10 = fmaxf(t10, __shfl_xor_sync(0xffffffffu, t10, 1));
        t10 = fmaxf(t10, __shfl_xor_sync(0xffffffffu, t10, 2));
        t11 = fmaxf(t11, __shfl_xor_sync(0xffffffffu, t11, 1));
        t11 = fmaxf(t11, __shfl_xor_sync(0xffffffffu, t11, 2));

        float n00 = fmaxf(m00, t00), n01 = fmaxf(m01, t01);
        float n10 = fmaxf(m10, t10), n11 = fmaxf(m11, t11);
        float a00 = ex2(m00 - n00), a01 = ex2(m01 - n01);
        float a10 = ex2(m10 - n10), a11 = ex2(m11 - n11);
        m00 = n00; m01 = n01; m10 = n10; m11 = n11;
        l00 *= a00; l01 *= a01; l10 *= a10; l11 *= a11;

        #pragma unroll
        for (int n = 0; n < 8; n++) {
            o0[n][0] *= a00; o0[n][1] *= a00;
            o0[n][2] *= a01; o0[n][3] *= a01;
            o1[n][0] *= a10; o1[n][1] *= a10;
            o1[n][2] *= a11; o1[n][3] *= a11;
            float p0 = ex2(c0[n][0] - n00);
            float p1 = ex2(c0[n][1] - n00);
            float p2 = ex2(c0[n][2] - n01);
            float p3 = ex2(c0[n][3] - n01);
            float p4 = ex2(c1[n][0] - n10);
            float p5 = ex2(c1[n][1] - n10);
            float p6 = ex2(c1[n][2] - n11);
            float p7 = ex2(c1[n][3] - n11);
            l00 += p0 + p1;  l01 += p2 + p3;
            l10 += p4 + p5;  l11 += p6 + p7;
            c0[n][0] = p0; c0[n][1] = p1; c0[n][2] = p2; c0[n][3] = p3;
            c1[n][0] = p4; c1[n][1] = p5; c1[n][2] = p6; c1[n][3] = p7;
        }

        // ---- write P (RNA tf32) to the private P buffer; own rows only
        #pragma unroll
        for (int n = 0; n < 8; n++) {
            *reinterpret_cast<float2*>(&sP[rw        * PSTR + n * 8 + 2 * qd]) =
                make_float2(f2tf32f(c0[n][0]), f2tf32f(c0[n][1]));
            *reinterpret_cast<float2*>(&sP[(rw + 8)  * PSTR + n * 8 + 2 * qd]) =
                make_float2(f2tf32f(c0[n][2]), f2tf32f(c0[n][3]));
            *reinterpret_cast<float2*>(&sP[(rw + 16) * PSTR + n * 8 + 2 * qd]) =
                make_float2(f2tf32f(c1[n][0]), f2tf32f(c1[n][1]));
            *reinterpret_cast<float2*>(&sP[(rw + 24) * PSTR + n * 8 + 2 * qd]) =
                make_float2(f2tf32f(c1[n][2]), f2tf32f(c1[n][3]));
        }
        __syncwarp();

        // ---- O += P V ; each V B-frag (RNA tf32) feeds 2 MMAs
        #pragma unroll
        for (int kk = 0; kk < 8; kk++) {
            uint32_t pa0[4], pa1[4];
            pa0[0] = __float_as_uint(sP[rw        * PSTR + kk * 8 + qd]);
            pa0[1] = __float_as_uint(sP[(rw + 8)  * PSTR + kk * 8 + qd]);
            pa0[2] = __float_as_uint(sP[rw        * PSTR + kk * 8 + qd + 4]);
            pa0[3] = __float_as_uint(sP[(rw + 8)  * PSTR + kk * 8 + qd + 4]);
            pa1[0] = __float_as_uint(sP[(rw + 16) * PSTR + kk * 8 + qd]);
            pa1[1] = __float_as_uint(sP[(rw + 24) * PSTR + kk * 8 + qd]);
            pa1[2] = __float_as_uint(sP[(rw + 16) * PSTR + kk * 8 + qd + 4]);
            pa1[3] = __float_as_uint(sP[(rw + 24) * PSTR + kk * 8 + qd + 4]);
            #pragma unroll
            for (int n = 0; n < 8; n++) {
                uint32_t vb[2];
                vb[0] = f2tf32(sV[(kk * 8 + qd)     * VSTR + n * 8 + g]);
                vb[1] = f2tf32(sV[(kk * 8 + qd + 4) * VSTR + n * 8 + g]);
                mma8(o0[n], pa0, vb);
                mma8(o1[n], pa1, vb);
            }
        }
    }

    // ---- finalize: quad-reduce l, normalize, store 4 row groups
    l00 += __shfl_xor_sync(0xffffffffu, l00, 1);
    l00 += __shfl_xor_sync(0xffffffffu, l00, 2);
    l01 += __shfl_xor_sync(0xffffffffu, l01, 1);
    l01 += __shfl_xor_sync(0xffffffffu, l01, 2);
    l10 += __shfl_xor_sync(0xffffffffu, l10, 1);
    l10 += __shfl_xor_sync(0xffffffffu, l10, 2);
    l11 += __shfl_xor_sync(0xffffffffu, l11, 1);
    l11 += __shfl_xor_sync(0xffffffffu, l11, 2);
    const float i00 = 1.f / l00, i01 = 1.f / l01;
    const float i10 = 1.f / l10, i11 = 1.f / l11;

    float* Oa0 = O + ((size_t)((size_t)b * SEQL + ga0) * NH + h) * HDIM;
    float* Oa1 = O + ((size_t)((size_t)b * SEQL + ga1) * NH + h) * HDIM;
    float* Ob0 = O + ((size_t)((size_t)b * SEQL + gb0) * NH + h) * HDIM;
    float* Ob1 = O + ((size_t)((size_t)b * SEQL + gb1) * NH + h) * HDIM;
    #pragma unroll
    for (int n = 0; n < 8; n++) {
        int col = n * 8 + 2 * qd;
        *reinterpret_cast<float2*>(Oa0 + col) =
            make_float2(o0[n][0] * i00, o0[n][1] * i00);
        *reinterpret_cast<float2*>(Oa1 + col) =
            make_float2(o0[n][2] * i01, o0[n][3] * i01);
        *reinterpret_cast<float2*>(Ob0 + col) =
            make_float2(o1[n][0] * i10, o1[n][1] * i10);
        *reinterpret_cast<float2*>(Ob1 + col) =
            make_float2(o1[n][2] * i11, o1[n][3] * i11);
    }
}

extern "C" void kernel_launch(void* const* d_in, const int* in_sizes, int n_in,
                              void* d_out, int out_size)
{
    const float* Q = (const float*)d_in[0];
    const float* K = (const float*)d_in[1];
    const float* V = (const float*)d_in[2];
    float* O = (float*)d_out;

    cudaFuncSetAttribute(fa_tf32_kernel,
                         cudaFuncAttributeMaxDynamicSharedMemorySize, SMEM_BYTES);

    dim3 grid(SEQL / BM, BATCH * NH);   // (16, 32)
    dim3 block(128);
    fa_tf32_kernel<<<grid, block, SMEM_BYTES>>>(Q, K, V, O);
}

// round 8
// speedup vs baseline: 1.5214x; 1.5214x over previous
#include <cuda_runtime.h>
#include <cuda_fp16.h>
#include <cstdint>
#include <math.h>

// Problem constants (fixed by the dataset)
#define BATCH 4
#define SEQL  2048
#define NH    8
#define HDIM  64
#define BM    64        // query rows per CTA (4 warps x 16)
#define BN    64        // key rows per iteration
#define RS    (NH * HDIM)   // 512 floats between seq positions
#define HKSTR 72        // fp16 tile row stride (halfs) — conflict-free frag reads

// smem layout (float units):
//   rawK  [64][64] fp32, 16B-granule XOR swizzle g^(r&7)        4096 floats
//   rawV  [64][64] fp32, granule swizzle g^((r>>1)&7)           4096 floats
//   hK    [64][72] half  (K, row-major)                         } 4608 floats
//   hVt   [64][72] half  (V transposed: [d][s])                 }  (9216 halfs)
//   (Q fp32 staging overlays the hK/hVt region in the prologue)
#define SMEM_FLOATS (8192 + 4608)
#define SMEM_BYTES  (SMEM_FLOATS * 4)    // 51200

__device__ __forceinline__ float ex2(float x) {
    float y;
    asm("ex2.approx.ftz.f32 %0, %1;" : "=f"(y) : "f"(x));
    return y;
}
__device__ __forceinline__ uint32_t packh2(float lo, float hi) {
    half2 h = __floats2half2_rn(lo, hi);
    return *reinterpret_cast<uint32_t*>(&h);
}

__device__ __forceinline__ void mma16(float c[4], const uint32_t a[4], const uint32_t b[2]) {
    asm volatile(
        "mma.sync.aligned.m16n8k16.row.col.f32.f16.f16.f32 "
        "{%0,%1,%2,%3}, {%4,%5,%6,%7}, {%8,%9}, {%0,%1,%2,%3};"
        : "+f"(c[0]), "+f"(c[1]), "+f"(c[2]), "+f"(c[3])
        : "r"(a[0]), "r"(a[1]), "r"(a[2]), "r"(a[3]),
          "r"(b[0]), "r"(b[1]));
}

__device__ __forceinline__ void cpasync16(uint32_t saddr, const float* g) {
    asm volatile("cp.async.cg.shared.global [%0], [%1], 16;\n"
                 :: "r"(saddr), "l"(g));
}

__global__ __launch_bounds__(128, 3)
void fa_fp16_kernel(const float* __restrict__ Q,
                    const float* __restrict__ K,
                    const float* __restrict__ V,
                    float* __restrict__ O)
{
    extern __shared__ float smem[];
    float* const rawK = smem;
    float* const rawV = smem + 4096;
    half*  const hK   = reinterpret_cast<half*>(smem + 8192);
    half*  const hVt  = hK + 64 * HKSTR;
    float* const sQf  = smem + 8192;     // prologue-only overlay

    const int tid  = threadIdx.x;
    const int warp = tid >> 5;
    const int lane = tid & 31;
    const int qd   = lane & 3;
    const int g    = lane >> 2;

    const int bh = blockIdx.y;
    const int b  = bh >> 3;
    const int h  = bh & 7;
    // heavy tiles first
    const int qblk = (SEQL / BM - 1) - blockIdx.x;
    const int m0   = qblk * BM;
    const int nblk = qblk + 1;

    const float qscale = 0.125f * 1.4426950408889634f;  // 1/sqrt(64) * log2(e)

    const float* Qb = Q + ((size_t)((size_t)b * SEQL + m0) * NH + h) * HDIM;
    const float* Kb = K + ((size_t)((size_t)b * SEQL) * NH + h) * HDIM;
    const float* Vb = V + ((size_t)((size_t)b * SEQL) * NH + h) * HDIM;

    // ---- prologue: async-load K/V tile 0 into swizzled raw stages
    #pragma unroll
    for (int i = 0; i < 8; i++) {
        int idx = i * 128 + tid;          // 64 rows x 16 granules
        int r   = idx >> 4;
        int gr  = idx & 15;
        size_t goff = (size_t)r * RS + 4 * gr;
        cpasync16((uint32_t)__cvta_generic_to_shared(rawK + r * 64 + 4 * (gr ^ (r & 7))), Kb + goff);
        cpasync16((uint32_t)__cvta_generic_to_shared(rawV + r * 64 + 4 * (gr ^ ((r >> 1) & 7))), Vb + goff);
    }
    asm volatile("cp.async.commit_group;\n");

    // ---- stage Q (fp32, stride 64) into overlay, then build fp16 A-frags
    #pragma unroll
    for (int i = 0; i < 8; i++) {
        int idx = i * 128 + tid;
        int r   = idx >> 4;
        int c4  = (idx & 15) << 2;
        float4 v = *reinterpret_cast<const float4*>(Qb + (size_t)r * RS + c4);
        float* dst = &sQf[r * 64 + c4];
        dst[0] = v.x; dst[1] = v.y; dst[2] = v.z; dst[3] = v.w;
    }
    __syncthreads();

    const int r0    = warp * 16 + g;
    const int grow0 = m0 + r0;
    const int grow1 = grow0 + 8;

    uint32_t qa[4][4];   // 4 K-steps of 16, m16n8k16 A-frags, scale folded in
    #pragma unroll
    for (int kk = 0; kk < 4; kk++) {
        const float* qr0 = &sQf[r0 * 64 + 16 * kk + 2 * qd];
        const float* qr1 = &sQf[(r0 + 8) * 64 + 16 * kk + 2 * qd];
        qa[kk][0] = packh2(qr0[0] * qscale, qr0[1] * qscale);
        qa[kk][1] = packh2(qr1[0] * qscale, qr1[1] * qscale);
        qa[kk][2] = packh2(qr0[8] * qscale, qr0[9] * qscale);
        qa[kk][3] = packh2(qr1[8] * qscale, qr1[9] * qscale);
    }
    // loop-top __syncthreads orders these reads before the pass overwrites sQf

    float o[8][4];
    #pragma unroll
    for (int n = 0; n < 8; n++)
        #pragma unroll
        for (int i = 0; i < 4; i++) o[n][i] = 0.f;

    float mrow0 = -INFINITY, mrow1 = -INFINITY;
    float l0 = 0.f, l1 = 0.f;

    for (int j = 0; j < nblk; j++) {
        asm volatile("cp.async.wait_group 0;\n");
        __syncthreads();   // raw tile j visible; fp16 bufs from j-1 fully consumed

        // ---- conversion pass: rawK -> hK (fp16), rawV -> hVt (fp16, transposed)
        // K: thread handles 8-half chunks; lanes vary rows -> conflict-free
        #pragma unroll
        for (int it = 0; it < 4; it++) {
            int p  = it * 128 + tid;
            int r  = p & 63;
            int c8 = (p >> 6) << 3;
            int g0 = (c8 >> 2) ^ (r & 7);
            int g1 = ((c8 >> 2) + 1) ^ (r & 7);
            float4 va = *reinterpret_cast<const float4*>(&rawK[r * 64 + 4 * g0]);
            float4 vb = *reinterpret_cast<const float4*>(&rawK[r * 64 + 4 * g1]);
            uint4 w;
            w.x = packh2(va.x, va.y);
            w.y = packh2(va.z, va.w);
            w.z = packh2(vb.x, vb.y);
            w.w = packh2(vb.z, vb.w);
            *reinterpret_cast<uint4*>(&hK[r * HKSTR + c8]) = w;
        }
        // V: transpose; lanes vary s2 -> conflict-free reads (swizzle) & writes
        #pragma unroll
        for (int it = 0; it < 4; it++) {
            int p  = it * 128 + tid;
            int s2 = p & 31;
            int dq = p >> 5;
            int gr = dq ^ (s2 & 7);
            float4 va = *reinterpret_cast<const float4*>(&rawV[(2 * s2) * 64 + 4 * gr]);
            float4 vb = *reinterpret_cast<const float4*>(&rawV[(2 * s2 + 1) * 64 + 4 * gr]);
            int d0 = 4 * dq;
            *reinterpret_cast<uint32_t*>(&hVt[(d0 + 0) * HKSTR + 2 * s2]) = packh2(va.x, vb.x);
            *reinterpret_cast<uint32_t*>(&hVt[(d0 + 1) * HKSTR + 2 * s2]) = packh2(va.y, vb.y);
            *reinterpret_cast<uint32_t*>(&hVt[(d0 + 2) * HKSTR + 2 * s2]) = packh2(va.z, vb.z);
            *reinterpret_cast<uint32_t*>(&hVt[(d0 + 3) * HKSTR + 2 * s2]) = packh2(va.w, vb.w);
        }
        __syncthreads();   // fp16 tiles visible; raw stage now free

        // ---- prefetch tile j+1 into the (now free) raw stage
        if (j + 1 < nblk) {
            #pragma unroll
            for (int i = 0; i < 8; i++) {
                int idx = i * 128 + tid;
                int r   = idx >> 4;
                int gr  = idx & 15;
                size_t goff = (size_t)((j + 1) * BN + r) * RS + 4 * gr;
                cpasync16((uint32_t)__cvta_generic_to_shared(rawK + r * 64 + 4 * (gr ^ (r & 7))), Kb + goff);
                cpasync16((uint32_t)__cvta_generic_to_shared(rawV + r * 64 + 4 * (gr ^ ((r >> 1) & 7))), Vb + goff);
            }
            asm volatile("cp.async.commit_group;\n");
        }

        // ---- S = Q K^T  (fp16 m16n8k16; 32 MMAs, 64 LDS.32)
        float c[8][4];
        #pragma unroll
        for (int n = 0; n < 8; n++)
            #pragma unroll
            for (int i = 0; i < 4; i++) c[n][i] = 0.f;

        #pragma unroll
        for (int kk = 0; kk < 4; kk++) {
            #pragma unroll
            for (int n = 0; n < 8; n++) {
                const half* kp = &hK[(8 * n + g) * HKSTR + 16 * kk + 2 * qd];
                uint32_t bf[2];
                bf[0] = *reinterpret_cast<const uint32_t*>(kp);
                bf[1] = *reinterpret_cast<const uint32_t*>(kp + 8);
                mma16(c[n], qa[kk], bf);
            }
        }

        // ---- causal mask (diagonal tile only)
        if (j == qblk) {
            #pragma unroll
            for (int n = 0; n < 8; n++) {
                int colb = j * BN + n * 8 + 2 * qd;
                if (colb     > grow0) c[n][0] = -INFINITY;
                if (colb + 1 > grow0) c[n][1] = -INFINITY;
                if (colb     > grow1) c[n][2] = -INFINITY;
                if (colb + 1 > grow1) c[n][3] = -INFINITY;
            }
        }

        // ---- online softmax (log2 domain; scale already in Q)
        float tm0 = -INFINITY, tm1 = -INFINITY;
        #pragma unroll
        for (int n = 0; n < 8; n++) {
            tm0 = fmaxf(tm0, fmaxf(c[n][0], c[n][1]));
            tm1 = fmaxf(tm1, fmaxf(c[n][2], c[n][3]));
        }
        tm0 = fmaxf(tm0, __shfl_xor_sync(0xffffffffu, tm0, 1));
        tm0 = fmaxf(tm0, __shfl_xor_sync(0xffffffffu, tm0, 2));
        tm1 = fmaxf(tm1, __shfl_xor_sync(0xffffffffu, tm1, 1));
        tm1 = fmaxf(tm1, __shfl_xor_sync(0xffffffffu, tm1, 2));

        float mn0 = fmaxf(mrow0, tm0);
        float mn1 = fmaxf(mrow1, tm1);
        float a0 = ex2(mrow0 - mn0);
        float a1 = ex2(mrow1 - mn1);
        mrow0 = mn0; mrow1 = mn1;
        l0 *= a0;  l1 *= a1;

        #pragma unroll
        for (int n = 0; n < 8; n++) {
            o[n][0] *= a0; o[n][1] *= a0;
            o[n][2] *= a1; o[n][3] *= a1;
            float p0 = ex2(c[n][0] - mn0);
            float p1 = ex2(c[n][1] - mn0);
            float p2 = ex2(c[n][2] - mn1);
            float p3 = ex2(c[n][3] - mn1);
            l0 += p0 + p1;
            l1 += p2 + p3;
            c[n][0] = p0; c[n][1] = p1; c[n][2] = p2; c[n][3] = p3;
        }

        // ---- O += P V : P stays in registers!  QK C-frag (rows g/g+8,
        // cols 8n+2qd) is exactly the m16n8k16 A-frag k-pair layout:
        //   a0 = P[g][16kk+2qd,+1]   = c[2kk][0..1]
        //   a1 = P[g+8][same]        = c[2kk][2..3]
        //   a2 = P[g][16kk+8+2qd,+1] = c[2kk+1][0..1]
        //   a3 = P[g+8][same]        = c[2kk+1][2..3]
        #pragma unroll
        for (int kk = 0; kk < 4; kk++) {
            uint32_t pa[4];
            pa[0] = packh2(c[2 * kk][0],     c[2 * kk][1]);
            pa[1] = packh2(c[2 * kk][2],     c[2 * kk][3]);
            pa[2] = packh2(c[2 * kk + 1][0], c[2 * kk + 1][1]);
            pa[3] = packh2(c[2 * kk + 1][2], c[2 * kk + 1][3]);
            #pragma unroll
            for (int n = 0; n < 8; n++) {
                const half* vp = &hVt[(8 * n + g) * HKSTR + 16 * kk + 2 * qd];
                uint32_t vb[2];
                vb[0] = *reinterpret_cast<const uint32_t*>(vp);
                vb[1] = *reinterpret_cast<const uint32_t*>(vp + 8);
                mma16(o[n], pa, vb);
            }
        }
    }

    // ---- finalize: quad-reduce l, normalize, store
    l0 += __shfl_xor_sync(0xffffffffu, l0, 1);
    l0 += __shfl_xor_sync(0xffffffffu, l0, 2);
    l1 += __shfl_xor_sync(0xffffffffu, l1, 1);
    l1 += __shfl_xor_sync(0xffffffffu, l1, 2);
    const float inv0 = 1.f / l0;
    const float inv1 = 1.f / l1;

    float* Ob0 = O + ((size_t)((size_t)b * SEQL + grow0) * NH + h) * HDIM;
    float* Ob1 = O + ((size_t)((size_t)b * SEQL + grow1) * NH + h) * HDIM;
    #pragma unroll
    for (int n = 0; n < 8; n++) {
        int col = n * 8 + 2 * qd;
        *reinterpret_cast<float2*>(Ob0 + col) =
            make_float2(o[n][0] * inv0, o[n][1] * inv0);
        *reinterpret_cast<float2*>(Ob1 + col) =
            make_float2(o[n][2] * inv1, o[n][3] * inv1);
    }
}

extern "C" void kernel_launch(void* const* d_in, const int* in_sizes, int n_in,
                              void* d_out, int out_size)
{
    const float* Q = (const float*)d_in[0];
    const float* K = (const float*)d_in[1];
    const float* V = (const float*)d_in[2];
    float* O = (float*)d_out;

    cudaFuncSetAttribute(fa_fp16_kernel,
                         cudaFuncAttributeMaxDynamicSharedMemorySize, SMEM_BYTES);

    dim3 grid(SEQL / BM, BATCH * NH);   // (32, 32)
    dim3 block(128);
    fa_fp16_kernel<<<grid, block, SMEM_BYTES>>>(Q, K, V, O);
}

// round 9
// speedup vs baseline: 1.8669x; 1.2271x over previous
#include <cuda_runtime.h>
#include <cuda_fp16.h>
#include <cstdint>
#include <math.h>

// Problem constants (fixed by the dataset)
#define BATCH 4
#define SEQL  2048
#define NH    8
#define HDIM  64
#define BM    64        // query rows per CTA (4 warps x 16)
#define BN    64        // key rows per iteration
#define RS    (NH * HDIM)   // 512 floats between seq positions
#define HSTR  72        // fp16 tile row stride (halfs) — conflict-free frag reads

// fp16 scratch: K as [b,h,s,e], V transposed as [b,h,d,s]
__device__ __half g_Kh[(size_t)BATCH * NH * SEQL * HDIM];
__device__ __half g_Vt[(size_t)BATCH * NH * HDIM * SEQL];

// stage = K tile (64x72 halfs) + V^T tile (64x72 halfs)
#define STAGE_HALFS (2 * BN * HSTR)              // 9216
#define SMEM_BYTES  (2 * STAGE_HALFS * 2)        // 36864 (double buffered)

__device__ __forceinline__ float ex2(float x) {
    float y;
    asm("ex2.approx.ftz.f32 %0, %1;" : "=f"(y) : "f"(x));
    return y;
}
__device__ __forceinline__ uint32_t packh2(float lo, float hi) {
    half2 h = __floats2half2_rn(lo, hi);
    return *reinterpret_cast<uint32_t*>(&h);
}

__device__ __forceinline__ void mma16(float c[4], const uint32_t a[4], const uint32_t b[2]) {
    asm volatile(
        "mma.sync.aligned.m16n8k16.row.col.f32.f16.f16.f32 "
        "{%0,%1,%2,%3}, {%4,%5,%6,%7}, {%8,%9}, {%0,%1,%2,%3};"
        : "+f"(c[0]), "+f"(c[1]), "+f"(c[2]), "+f"(c[3])
        : "r"(a[0]), "r"(a[1]), "r"(a[2]), "r"(a[3]),
          "r"(b[0]), "r"(b[1]));
}

__device__ __forceinline__ void cpasync16(uint32_t saddr, const void* g) {
    asm volatile("cp.async.cg.shared.global [%0], [%1], 16;\n"
                 :: "r"(saddr), "l"(g));
}

// ---------------- prepass 1: K [b,s,h,e] fp32 -> g_Kh [b,h,s,e] fp16 ----------------
__global__ void convK_kernel(const float* __restrict__ K)
{
    int lin = blockIdx.x * 256 + threadIdx.x;    // one float4 (4 e-values) each
    int e4 = lin & 15;
    int h  = (lin >> 4) & 7;
    int s  = (lin >> 7) & 2047;
    int b  = lin >> 18;
    float4 v = reinterpret_cast<const float4*>(K)[lin];
    size_t o = (((size_t)(b * 8 + h) * SEQL + s) * 16 + e4) * 2;   // half2 units
    reinterpret_cast<__half2*>(g_Kh)[o]     = __floats2half2_rn(v.x, v.y);
    reinterpret_cast<__half2*>(g_Kh)[o + 1] = __floats2half2_rn(v.z, v.w);
}

// ---------------- prepass 2: V [b,s,h,d] fp32 -> g_Vt [b,h,d,s] fp16 ----------------
__global__ void convV_kernel(const float* __restrict__ V)
{
    __shared__ float st[64 * 65];
    const int bh = blockIdx.y;
    const int b  = bh >> 3;
    const int h  = bh & 7;
    const int s0 = blockIdx.x * 64;
    const int tid = threadIdx.x;   // 256

    #pragma unroll
    for (int i = 0; i < 4; i++) {
        int idx = i * 256 + tid;           // 64 rows x 16 float4
        int r   = idx >> 4;
        int c4  = (idx & 15) << 2;
        float4 v = *reinterpret_cast<const float4*>(
            V + ((size_t)((size_t)b * SEQL + s0 + r) * NH + h) * HDIM + c4);
        float* dst = &st[r * 65 + c4];
        dst[0] = v.x; dst[1] = v.y; dst[2] = v.z; dst[3] = v.w;
    }
    __syncthreads();

    __half* out = g_Vt + ((size_t)(b * 8 + h) * HDIM) * SEQL;
    #pragma unroll
    for (int i = 0; i < 8; i++) {
        int idx = i * 256 + tid;           // 64 d x 32 s-pairs
        int d   = idx >> 5;
        int s2  = idx & 31;
        __half2 w = __floats2half2_rn(st[(2 * s2) * 65 + d],
                                      st[(2 * s2 + 1) * 65 + d]);
        *reinterpret_cast<__half2*>(out + (size_t)d * SEQL + s0 + 2 * s2) = w;
    }
}

// ---------------- main attention kernel ----------------
__global__ __launch_bounds__(128, 3)
void fa_fp16_kernel(const float* __restrict__ Q,
                    float* __restrict__ O)
{
    extern __shared__ __half sh[];
    __half* const stage0 = sh;
    __half* const stage1 = sh + STAGE_HALFS;
    float*  const sQf    = reinterpret_cast<float*>(stage1);   // prologue overlay (16KB<18KB)

    const int tid  = threadIdx.x;
    const int warp = tid >> 5;
    const int lane = tid & 31;
    const int qd   = lane & 3;
    const int g    = lane >> 2;

    const int bh = blockIdx.y;
    const int b  = bh >> 3;
    const int h  = bh & 7;
    // heavy tiles first
    const int qblk = (SEQL / BM - 1) - blockIdx.x;
    const int m0   = qblk * BM;
    const int nblk = qblk + 1;

    const float qscale = 0.125f * 1.4426950408889634f;  // 1/sqrt(64) * log2(e)

    const float*  Qb  = Q + ((size_t)((size_t)b * SEQL + m0) * NH + h) * HDIM;
    const __half* Khb = g_Kh + (size_t)(b * 8 + h) * SEQL * HDIM;
    const __half* Vtb = g_Vt + (size_t)(b * 8 + h) * HDIM * SEQL;

    // ---- prologue: async-load fp16 tile 0 directly into fragment layout
    {
        __half* dK = stage0;
        __half* dV = stage0 + BN * HSTR;
        #pragma unroll
        for (int i = 0; i < 4; i++) {
            int idx = i * 128 + tid;       // 64 rows x 8 chunks of 16B
            int r   = idx >> 3;
            int gr  = idx & 7;
            cpasync16((uint32_t)__cvta_generic_to_shared(dK + r * HSTR + 8 * gr),
                      Khb + (size_t)r * HDIM + 8 * gr);
            cpasync16((uint32_t)__cvta_generic_to_shared(dV + r * HSTR + 8 * gr),
                      Vtb + (size_t)r * SEQL + 8 * gr);
        }
        asm volatile("cp.async.commit_group;\n");
    }

    // ---- stage Q (fp32) into overlay, build fp16 A-frags with scale folded in
    #pragma unroll
    for (int i = 0; i < 8; i++) {
        int idx = i * 128 + tid;
        int r   = idx >> 4;
        int c4  = (idx & 15) << 2;
        float4 v = *reinterpret_cast<const float4*>(Qb + (size_t)r * RS + c4);
        float* dst = &sQf[r * 64 + c4];
        dst[0] = v.x; dst[1] = v.y; dst[2] = v.z; dst[3] = v.w;
    }
    __syncthreads();

    const int r0    = warp * 16 + g;
    const int grow0 = m0 + r0;
    const int grow1 = grow0 + 8;

    uint32_t qa[4][4];
    #pragma unroll
    for (int kk = 0; kk < 4; kk++) {
        const float* qr0 = &sQf[r0 * 64 + 16 * kk + 2 * qd];
        const float* qr1 = &sQf[(r0 + 8) * 64 + 16 * kk + 2 * qd];
        qa[kk][0] = packh2(qr0[0] * qscale, qr0[1] * qscale);
        qa[kk][1] = packh2(qr1[0] * qscale, qr1[1] * qscale);
        qa[kk][2] = packh2(qr0[8] * qscale, qr0[9] * qscale);
        qa[kk][3] = packh2(qr1[8] * qscale, qr1[9] * qscale);
    }
    // j=0 loop-top barrier orders these reads before prefetch j=1 overwrites stage1

    float o[8][4];
    #pragma unroll
    for (int n = 0; n < 8; n++)
        #pragma unroll
        for (int i = 0; i < 4; i++) o[n][i] = 0.f;

    float mrow0 = -INFINITY, mrow1 = -INFINITY;
    float l0 = 0.f, l1 = 0.f;

    for (int j = 0; j < nblk; j++) {
        __half* const st = (j & 1) ? stage1 : stage0;
        const __half* const hK  = st;
        const __half* const hVt = st + BN * HSTR;

        asm volatile("cp.async.wait_group 0;\n");
        __syncthreads();   // tile j visible; all warps done reading stage[(j+1)&1] (iter j-1)

        // ---- prefetch tile j+1 (overlaps all of this iteration's compute)
        if (j + 1 < nblk) {
            __half* const nst = (j & 1) ? stage0 : stage1;
            __half* dK = nst;
            __half* dV = nst + BN * HSTR;
            #pragma unroll
            for (int i = 0; i < 4; i++) {
                int idx = i * 128 + tid;
                int r   = idx >> 3;
                int gr  = idx & 7;
                cpasync16((uint32_t)__cvta_generic_to_shared(dK + r * HSTR + 8 * gr),
                          Khb + (size_t)(j + 1) * BN * HDIM + (size_t)r * HDIM + 8 * gr);
                cpasync16((uint32_t)__cvta_generic_to_shared(dV + r * HSTR + 8 * gr),
                          Vtb + (size_t)r * SEQL + (j + 1) * BN + 8 * gr);
            }
            asm volatile("cp.async.commit_group;\n");
        }

        // ---- S = Q K^T  (fp16 m16n8k16)
        float c[8][4];
        #pragma unroll
        for (int n = 0; n < 8; n++)
            #pragma unroll
            for (int i = 0; i < 4; i++) c[n][i] = 0.f;

        #pragma unroll
        for (int kk = 0; kk < 4; kk++) {
            #pragma unroll
            for (int n = 0; n < 8; n++) {
                const __half* kp = &hK[(8 * n + g) * HSTR + 16 * kk + 2 * qd];
                uint32_t bf[2];
                bf[0] = *reinterpret_cast<const uint32_t*>(kp);
                bf[1] = *reinterpret_cast<const uint32_t*>(kp + 8);
                mma16(c[n], qa[kk], bf);
            }
        }

        // ---- causal mask (diagonal tile only)
        if (j == qblk) {
            #pragma unroll
            for (int n = 0; n < 8; n++) {
                int colb = j * BN + n * 8 + 2 * qd;
                if (colb     > grow0) c[n][0] = -INFINITY;
                if (colb + 1 > grow0) c[n][1] = -INFINITY;
                if (colb     > grow1) c[n][2] = -INFINITY;
                if (colb + 1 > grow1) c[n][3] = -INFINITY;
            }
        }

        // ---- online softmax (log2 domain; scale already in Q)
        float tm0 = -INFINITY, tm1 = -INFINITY;
        #pragma unroll
        for (int n = 0; n < 8; n++) {
            tm0 = fmaxf(tm0, fmaxf(c[n][0], c[n][1]));
            tm1 = fmaxf(tm1, fmaxf(c[n][2], c[n][3]));
        }
        tm0 = fmaxf(tm0, __shfl_xor_sync(0xffffffffu, tm0, 1));
        tm0 = fmaxf(tm0, __shfl_xor_sync(0xffffffffu, tm0, 2));
        tm1 = fmaxf(tm1, __shfl_xor_sync(0xffffffffu, tm1, 1));
        tm1 = fmaxf(tm1, __shfl_xor_sync(0xffffffffu, tm1, 2));

        float mn0 = fmaxf(mrow0, tm0);
        float mn1 = fmaxf(mrow1, tm1);
        float a0 = ex2(mrow0 - mn0);
        float a1 = ex2(mrow1 - mn1);
        mrow0 = mn0; mrow1 = mn1;
        l0 *= a0;  l1 *= a1;

        #pragma unroll
        for (int n = 0; n < 8; n++) {
            o[n][0] *= a0; o[n][1] *= a0;
            o[n][2] *= a1; o[n][3] *= a1;
            float p0 = ex2(c[n][0] - mn0);
            float p1 = ex2(c[n][1] - mn0);
            float p2 = ex2(c[n][2] - mn1);
            float p3 = ex2(c[n][3] - mn1);
            l0 += p0 + p1;
            l1 += p2 + p3;
            c[n][0] = p0; c[n][1] = p1; c[n][2] = p2; c[n][3] = p3;
        }

        // ---- O += P V : P stays in registers (QK C-frag == PV A-frag layout)
        #pragma unroll
        for (int kk = 0; kk < 4; kk++) {
            uint32_t pa[4];
            pa[0] = packh2(c[2 * kk][0],     c[2 * kk][1]);
            pa[1] = packh2(c[2 * kk][2],     c[2 * kk][3]);
            pa[2] = packh2(c[2 * kk + 1][0], c[2 * kk + 1][1]);
            pa[3] = packh2(c[2 * kk + 1][2], c[2 * kk + 1][3]);
            #pragma unroll
            for (int n = 0; n < 8; n++) {
                const __half* vp = &hVt[(8 * n + g) * HSTR + 16 * kk + 2 * qd];
                uint32_t vb[2];
                vb[0] = *reinterpret_cast<const uint32_t*>(vp);
                vb[1] = *reinterpret_cast<const uint32_t*>(vp + 8);
                mma16(o[n], pa, vb);
            }
        }
    }

    // ---- finalize: quad-reduce l, normalize, store
    l0 += __shfl_xor_sync(0xffffffffu, l0, 1);
    l0 += __shfl_xor_sync(0xffffffffu, l0, 2);
    l1 += __shfl_xor_sync(0xffffffffu, l1, 1);
    l1 += __shfl_xor_sync(0xffffffffu, l1, 2);
    const float inv0 = 1.f / l0;
    const float inv1 = 1.f / l1;

    float* Ob0 = O + ((size_t)((size_t)b * SEQL + grow0) * NH + h) * HDIM;
    float* Ob1 = O + ((size_t)((size_t)b * SEQL + grow1) * NH + h) * HDIM;
    #pragma unroll
    for (int n = 0; n < 8; n++) {
        int col = n * 8 + 2 * qd;
        *reinterpret_cast<float2*>(Ob0 + col) =
            make_float2(o[n][0] * inv0, o[n][1] * inv0);
        *reinterpret_cast<float2*>(Ob1 + col) =
            make_float2(o[n][2] * inv1, o[n][3] * inv1);
    }
}

extern "C" void kernel_launch(void* const* d_in, const int* in_sizes, int n_in,
                              void* d_out, int out_size)
{
    const float* Q = (const float*)d_in[0];
    const float* K = (const float*)d_in[1];
    const float* V = (const float*)d_in[2];
    float* O = (float*)d_out;

    // prepass: fp16 conversion (K relayout, V transpose) — once per launch
    convK_kernel<<<(BATCH * SEQL * NH * HDIM / 4) / 256, 256>>>(K);
    convV_kernel<<<dim3(SEQL / 64, BATCH * NH), 256>>>(V);

    cudaFuncSetAttribute(fa_fp16_kernel,
                         cudaFuncAttributeMaxDynamicSharedMemorySize, SMEM_BYTES);
    dim3 grid(SEQL / BM, BATCH * NH);   // (32, 32)
    fa_fp16_kernel<<<grid, 128, SMEM_BYTES>>>(Q, O);
}

// round 10
// speedup vs baseline: 1.9936x; 1.0678x over previous
#include <cuda_runtime.h>
#include <cuda_fp16.h>
#include <cstdint>
#include <math.h>

// Problem constants (fixed by the dataset)
#define BATCH 4
#define SEQL  2048
#define NH    8
#define HDIM  64
#define BM    64        // query rows per CTA (4 warps x 16)
#define BN    64        // key rows per iteration
#define RS    (NH * HDIM)   // 512 floats between seq positions
#define HSTR  72        // fp16 tile row stride (halfs)

// fp16 scratch: K as [b,h,s,e], V transposed as [b,h,d,s]
__device__ __half g_Kh[(size_t)BATCH * NH * SEQL * HDIM];
__device__ __half g_Vt[(size_t)BATCH * NH * HDIM * SEQL];

#define STAGE_HALFS (2 * BN * HSTR)              // 9216
#define SMEM_BYTES  (2 * STAGE_HALFS * 2)        // 36864 (double buffered)

__device__ __forceinline__ float ex2(float x) {
    float y;
    asm("ex2.approx.ftz.f32 %0, %1;" : "=f"(y) : "f"(x));
    return y;
}
__device__ __forceinline__ uint32_t packh2(float lo, float hi) {
    half2 h = __floats2half2_rn(lo, hi);
    return *reinterpret_cast<uint32_t*>(&h);
}

__device__ __forceinline__ void mma16(float c[4], const uint32_t a[4],
                                      uint32_t b0, uint32_t b1) {
    asm volatile(
        "mma.sync.aligned.m16n8k16.row.col.f32.f16.f16.f32 "
        "{%0,%1,%2,%3}, {%4,%5,%6,%7}, {%8,%9}, {%0,%1,%2,%3};"
        : "+f"(c[0]), "+f"(c[1]), "+f"(c[2]), "+f"(c[3])
        : "r"(a[0]), "r"(a[1]), "r"(a[2]), "r"(a[3]),
          "r"(b0), "r"(b1));
}

__device__ __forceinline__ void ldsm4(uint32_t r[4], uint32_t saddr) {
    asm volatile("ldmatrix.sync.aligned.m8n8.x4.shared.b16 {%0,%1,%2,%3}, [%4];"
        : "=r"(r[0]), "=r"(r[1]), "=r"(r[2]), "=r"(r[3]) : "r"(saddr));
}

__device__ __forceinline__ void cpasync16(uint32_t saddr, const void* g) {
    asm volatile("cp.async.cg.shared.global [%0], [%1], 16;\n"
                 :: "r"(saddr), "l"(g));
}

// ---------------- fused prepass: K relayout + V transpose, both fp32->fp16 ----------------
__global__ void conv_kernel(const float* __restrict__ K, const float* __restrict__ V)
{
    __shared__ float st[64 * 65];
    const int bh = blockIdx.y;
    const int b  = bh >> 3;
    const int h  = bh & 7;
    const int s0 = blockIdx.x * 64;
    const int tid = threadIdx.x;   // 256

    // K: [b,s,h,e] -> g_Kh [b,h,s,e] (straight convert, coalesced both sides)
    __half* outK = g_Kh + (size_t)bh * SEQL * HDIM;
    #pragma unroll
    for (int i = 0; i < 4; i++) {
        int idx = i * 256 + tid;           // 64 rows x 16 float4
        int r   = idx >> 4;
        int c4  = (idx & 15) << 2;
        float4 v = *reinterpret_cast<const float4*>(
            K + ((size_t)((size_t)b * SEQL + s0 + r) * NH + h) * HDIM + c4);
        uint2 w;
        w.x = packh2(v.x, v.y);
        w.y = packh2(v.z, v.w);
        *reinterpret_cast<uint2*>(outK + (size_t)(s0 + r) * HDIM + c4) = w;
    }

    // V: [b,s,h,d] -> g_Vt [b,h,d,s] (transpose via smem)
    #pragma unroll
    for (int i = 0; i < 4; i++) {
        int idx = i * 256 + tid;
        int r   = idx >> 4;
        int c4  = (idx & 15) << 2;
        float4 v = *reinterpret_cast<const float4*>(
            V + ((size_t)((size_t)b * SEQL + s0 + r) * NH + h) * HDIM + c4);
        float* dst = &st[r * 65 + c4];
        dst[0] = v.x; dst[1] = v.y; dst[2] = v.z; dst[3] = v.w;
    }
    __syncthreads();

    __half* outV = g_Vt + (size_t)bh * HDIM * SEQL;
    #pragma unroll
    for (int i = 0; i < 8; i++) {
        int idx = i * 256 + tid;           // 64 d x 32 s-pairs
        int d   = idx >> 5;
        int s2  = idx & 31;
        __half2 w = __floats2half2_rn(st[(2 * s2) * 65 + d],
                                      st[(2 * s2 + 1) * 65 + d]);
        *reinterpret_cast<__half2*>(outV + (size_t)d * SEQL + s0 + 2 * s2) = w;
    }
}

// ---------------- main attention kernel ----------------
__global__ __launch_bounds__(128, 3)
void fa_fp16_kernel(const float* __restrict__ Q,
                    float* __restrict__ O)
{
    extern __shared__ __half sh[];
    __half* const stage0 = sh;
    __half* const stage1 = sh + STAGE_HALFS;
    float*  const sQf    = reinterpret_cast<float*>(stage1);   // prologue overlay

    const int tid  = threadIdx.x;
    const int warp = tid >> 5;
    const int lane = tid & 31;
    const int qd   = lane & 3;
    const int g    = lane >> 2;

    const int bh = blockIdx.y;
    const int b  = bh >> 3;
    const int h  = bh & 7;
    // heavy tiles first
    const int qblk = (SEQL / BM - 1) - blockIdx.x;
    const int m0   = qblk * BM;
    const int nblk = qblk + 1;

    const float qscale = 0.125f * 1.4426950408889634f;  // 1/sqrt(64) * log2(e)

    const float*  Qb  = Q + ((size_t)((size_t)b * SEQL + m0) * NH + h) * HDIM;
    const __half* Khb = g_Kh + (size_t)bh * SEQL * HDIM;
    const __half* Vtb = g_Vt + (size_t)bh * HDIM * SEQL;

    // per-lane ldmatrix row offset (halfs): row lane&7, matrix lane>>3
    const int lrow = (lane & 7) * HSTR + 8 * (lane >> 3);

    // ---- prologue: async-load fp16 tile 0 directly into fragment layout
    {
        __half* dK = stage0;
        __half* dV = stage0 + BN * HSTR;
        #pragma unroll
        for (int i = 0; i < 4; i++) {
            int idx = i * 128 + tid;       // 64 rows x 8 chunks of 16B
            int r   = idx >> 3;
            int gr  = idx & 7;
            cpasync16((uint32_t)__cvta_generic_to_shared(dK + r * HSTR + 8 * gr),
                      Khb + (size_t)r * HDIM + 8 * gr);
            cpasync16((uint32_t)__cvta_generic_to_shared(dV + r * HSTR + 8 * gr),
                      Vtb + (size_t)r * SEQL + 8 * gr);
        }
        asm volatile("cp.async.commit_group;\n");
    }

    // ---- stage Q (fp32) into overlay, build fp16 A-frags with scale folded in
    #pragma unroll
    for (int i = 0; i < 8; i++) {
        int idx = i * 128 + tid;
        int r   = idx >> 4;
        int c4  = (idx & 15) << 2;
        float4 v = *reinterpret_cast<const float4*>(Qb + (size_t)r * RS + c4);
        float* dst = &sQf[r * 64 + c4];
        dst[0] = v.x; dst[1] = v.y; dst[2] = v.z; dst[3] = v.w;
    }
    __syncthreads();

    const int r0    = warp * 16 + g;
    const int grow0 = m0 + r0;
    const int grow1 = grow0 + 8;

    uint32_t qa[4][4];
    #pragma unroll
    for (int kk = 0; kk < 4; kk++) {
        const float* qr0 = &sQf[r0 * 64 + 16 * kk + 2 * qd];
        const float* qr1 = &sQf[(r0 + 8) * 64 + 16 * kk + 2 * qd];
        qa[kk][0] = packh2(qr0[0] * qscale, qr0[1] * qscale);
        qa[kk][1] = packh2(qr1[0] * qscale, qr1[1] * qscale);
        qa[kk][2] = packh2(qr0[8] * qscale, qr0[9] * qscale);
        qa[kk][3] = packh2(qr1[8] * qscale, qr1[9] * qscale);
    }

    float o[8][4];
    #pragma unroll
    for (int n = 0; n < 8; n++)
        #pragma unroll
        for (int i = 0; i < 4; i++) o[n][i] = 0.f;

    float mrow0 = -INFINITY, mrow1 = -INFINITY;
    float l0 = 0.f, l1 = 0.f;

    for (int j = 0; j < nblk; j++) {
        __half* const st = (j & 1) ? stage1 : stage0;
        const uint32_t kbase = (uint32_t)__cvta_generic_to_shared(st) + lrow * 2;
        const uint32_t vbase = kbase + BN * HSTR * 2;

        asm volatile("cp.async.wait_group 0;\n");
        __syncthreads();   // tile j visible; stage[(j+1)&1] fully consumed

        // ---- prefetch tile j+1
        if (j + 1 < nblk) {
            __half* const nst = (j & 1) ? stage0 : stage1;
            __half* dK = nst;
            __half* dV = nst + BN * HSTR;
            #pragma unroll
            for (int i = 0; i < 4; i++) {
                int idx = i * 128 + tid;
                int r   = idx >> 3;
                int gr  = idx & 7;
                cpasync16((uint32_t)__cvta_generic_to_shared(dK + r * HSTR + 8 * gr),
                          Khb + (size_t)(j + 1) * BN * HDIM + (size_t)r * HDIM + 8 * gr);
                cpasync16((uint32_t)__cvta_generic_to_shared(dV + r * HSTR + 8 * gr),
                          Vtb + (size_t)r * SEQL + (j + 1) * BN + 8 * gr);
            }
            asm volatile("cp.async.commit_group;\n");
        }

        // ---- S = Q K^T : B-frags via ldmatrix.x4 (2 LDSM per n vs 8 LDS.32)
        float c[8][4];
        #pragma unroll
        for (int n = 0; n < 8; n++)
            #pragma unroll
            for (int i = 0; i < 4; i++) c[n][i] = 0.f;

        #pragma unroll
        for (int n = 0; n < 8; n++) {
            uint32_t kb[8];
            uint32_t a0 = kbase + (8 * n * HSTR) * 2;
            ldsm4(kb,     a0);          // matrices kc=0..3 -> b0/b1 for kk=0,1
            ldsm4(kb + 4, a0 + 64);     // matrices kc=4..7 -> b0/b1 for kk=2,3
            mma16(c[n], qa[0], kb[0], kb[1]);
            mma16(c[n], qa[1], kb[2], kb[3]);
            mma16(c[n], qa[2], kb[4], kb[5]);
            mma16(c[n], qa[3], kb[6], kb[7]);
        }

        // ---- causal mask (diagonal tile only)
        if (j == qblk) {
            #pragma unroll
            for (int n = 0; n < 8; n++) {
                int colb = j * BN + n * 8 + 2 * qd;
                if (colb     > grow0) c[n][0] = -INFINITY;
                if (colb + 1 > grow0) c[n][1] = -INFINITY;
                if (colb     > grow1) c[n][2] = -INFINITY;
                if (colb + 1 > grow1) c[n][3] = -INFINITY;
            }
        }

        // ---- online softmax (log2 domain; scale already in Q)
        float tm0 = -INFINITY, tm1 = -INFINITY;
        #pragma unroll
        for (int n = 0; n < 8; n++) {
            tm0 = fmaxf(tm0, fmaxf(c[n][0], c[n][1]));
            tm1 = fmaxf(tm1, fmaxf(c[n][2], c[n][3]));
        }
        tm0 = fmaxf(tm0, __shfl_xor_sync(0xffffffffu, tm0, 1));
        tm0 = fmaxf(tm0, __shfl_xor_sync(0xffffffffu, tm0, 2));
        tm1 = fmaxf(tm1, __shfl_xor_sync(0xffffffffu, tm1, 1));
        tm1 = fmaxf(tm1, __shfl_xor_sync(0xffffffffu, tm1, 2));

        float mn0 = fmaxf(mrow0, tm0);
        float mn1 = fmaxf(mrow1, tm1);
        float a0 = ex2(mrow0 - mn0);
        float a1 = ex2(mrow1 - mn1);
        mrow0 = mn0; mrow1 = mn1;
        l0 *= a0;  l1 *= a1;

        #pragma unroll
        for (int n = 0; n < 8; n++) {
            o[n][0] *= a0; o[n][1] *= a0;
            o[n][2] *= a1; o[n][3] *= a1;
            float p0 = ex2(c[n][0] - mn0);
            float p1 = ex2(c[n][1] - mn0);
            float p2 = ex2(c[n][2] - mn1);
            float p3 = ex2(c[n][3] - mn1);
            l0 += p0 + p1;
            l1 += p2 + p3;
            c[n][0] = p0; c[n][1] = p1; c[n][2] = p2; c[n][3] = p3;
        }

        // ---- O += P V : P in registers (QK C-frag == PV A-frag layout)
        uint32_t pa[4][4];
        #pragma unroll
        for (int kk = 0; kk < 4; kk++) {
            pa[kk][0] = packh2(c[2 * kk][0],     c[2 * kk][1]);
            pa[kk][1] = packh2(c[2 * kk][2],     c[2 * kk][3]);
            pa[kk][2] = packh2(c[2 * kk + 1][0], c[2 * kk + 1][1]);
            pa[kk][3] = packh2(c[2 * kk + 1][2], c[2 * kk + 1][3]);
        }
        #pragma unroll
        for (int n = 0; n < 8; n++) {
            uint32_t vb[8];
            uint32_t a0 = vbase + (8 * n * HSTR) * 2;
            ldsm4(vb,     a0);
            ldsm4(vb + 4, a0 + 64);
            mma16(o[n], pa[0], vb[0], vb[1]);
            mma16(o[n], pa[1], vb[2], vb[3]);
            mma16(o[n], pa[2], vb[4], vb[5]);
            mma16(o[n], pa[3], vb[6], vb[7]);
        }
    }

    // ---- finalize: quad-reduce l, normalize, store
    l0 += __shfl_xor_sync(0xffffffffu, l0, 1);
    l0 += __shfl_xor_sync(0xffffffffu, l0, 2);
    l1 += __shfl_xor_sync(0xffffffffu, l1, 1);
    l1 += __shfl_xor_sync(0xffffffffu, l1, 2);
    const float inv0 = 1.f / l0;
    const float inv1 = 1.f / l1;

    float* Ob0 = O + ((size_t)((size_t)b * SEQL + grow0) * NH + h) * HDIM;
    float* Ob1 = O + ((size_t)((size_t)b * SEQL + grow1) * NH + h) * HDIM;
    #pragma unroll
    for (int n = 0; n < 8; n++) {
        int col = n * 8 + 2 * qd;
        *reinterpret_cast<float2*>(Ob0 + col) =
            make_float2(o[n][0] * inv0, o[n][1] * inv0);
        *reinterpret_cast<float2*>(Ob1 + col) =
            make_float2(o[n][2] * inv1, o[n][3] * inv1);
    }
}

extern "C" void kernel_launch(void* const* d_in, const int* in_sizes, int n_in,
                              void* d_out, int out_size)
{
    const float* Q = (const float*)d_in[0];
    const float* K = (const float*)d_in[1];
    const float* V = (const float*)d_in[2];
    float* O = (float*)d_out;

    // fused prepass: K relayout + V transpose to fp16 scratch
    conv_kernel<<<dim3(SEQL / 64, BATCH * NH), 256>>>(K, V);

    cudaFuncSetAttribute(fa_fp16_kernel,
                         cudaFuncAttributeMaxDynamicSharedMemorySize, SMEM_BYTES);
    dim3 grid(SEQL / BM, BATCH * NH);   // (32, 32)
    fa_fp16_kernel<<<grid, 128, SMEM_BYTES>>>(Q, O);
}